// round 11
// baseline (speedup 1.0000x reference)
#include <cuda_runtime.h>

// Fixed shapes
#define B_   16
#define J_   1024
#define L_   4096
#define D4   128          // D/4 float4 lanes
#define NCH  32           // chunks along J
#define CLEN 32           // J per chunk
#define NSG  4            // subgroups per chunk (inside block)
#define SLEN 8            // J per subgroup
#define EPSV 1e-4f

// Scratch (device globals; zero-initialized at load, flags re-zeroed by gather)
__device__ float4 g_partialEnd[B_ * NCH * D4];     // chunk-local end states
__device__ unsigned long long g_flag[B_ * NCH];    // hi32=valid, lo32=A bits
__device__ float4 g_smoothed[B_ * J_ * D4];        // FINAL smoothed, 32 MiB
__device__ int    g_idx[B_ * L_];                  // gather indices

// ---------------------------------------------------------------------------
// Kernel 1: grid ((NCH+1), B), 512 threads.
//  blocks c<NCH : chunk EMA + decoupled lookback -> fully corrected smoothed
//  blocks c==NCH: boundary-mask scan -> gather indices for batch b
// ---------------------------------------------------------------------------
__global__ void __launch_bounds__(512, 2)
k_partial(const float4* __restrict__ emb,
          const float*  __restrict__ conf,
          const int*    __restrict__ mask,
          const int*    __restrict__ bnd) {
    const int c = blockIdx.x, b = blockIdx.y, t = threadIdx.x;

    if (c == NCH) {
        // ---- boundary scan -> gather idx: 512 threads, 8 elems/thread ----
        const int lane = t & 31, w = t >> 5;    // 16 warps
        __shared__ int wsum[16];

        const int* p = bnd + b * L_ + t * 8;
        int v[8];
        int s = 0;
        #pragma unroll
        for (int i = 0; i < 8; i++) { v[i] = p[i]; s += (v[i] != 0); }

        int incl = s;
        #pragma unroll
        for (int off = 1; off < 32; off <<= 1) {
            int u = __shfl_up_sync(0xFFFFFFFFu, incl, off);
            if (lane >= off) incl += u;
        }
        if (lane == 31) wsum[w] = incl;
        __syncthreads();
        if (t < 16) {
            int x = wsum[t];
            #pragma unroll
            for (int off = 1; off < 16; off <<= 1) {
                int u = __shfl_up_sync(0x0000FFFFu, x, off);
                if (t >= off) x += u;
            }
            wsum[t] = x;
        }
        __syncthreads();

        int run = incl - s + (w ? wsum[w - 1] : 0);   // exclusive prefix
        int* op = g_idx + b * L_ + t * 8;
        #pragma unroll
        for (int i = 0; i < 8; i++) {
            run += (v[i] != 0);
            int id = run - 1;
            id = id < 0 ? 0 : (id > (J_ - 1) ? (J_ - 1) : id);
            op[i] = id;
        }
        return;
    }

    // ---- EMA chunk scan with decoupled lookback ----
    const int g = t >> 7, d4 = t & 127;

    __shared__ float  sa[CLEN], sb[CLEN], sSeg[CLEN], sGA[NSG], sPF[CLEN];
    __shared__ float  sChunkA;
    __shared__ float  sP[32];
    __shared__ float4 sVec[NSG][D4];   // phase 1: subgroup ends; phase 2: carry partials

    // 1) prefetch emb (streaming; independent of prologue)
    const int jb = g * SLEN;
    const size_t base = ((size_t)b * J_ + (size_t)c * CLEN + jb) * D4 + d4;
    const float4* ep = emb + base;
    float4 e[SLEN];
    #pragma unroll
    for (int i = 0; i < SLEN; i++) e[i] = __ldcs(ep + (size_t)i * D4);

    // 2) warp-0 prologue
    if (t < CLEN) {
        const int j = c * CLEN + t;
        float p = conf[b * J_ + j];
        p = fminf(fmaxf(p, EPSV), 1.0f - EPSV);
        const bool m = mask[b * J_ + j] != 0;
        const float a = m ? (1.0f - p) : 1.0f;
        sa[t] = a;
        sb[t] = m ? p : 0.0f;

        // width-32 inclusive product -> within-chunk weight pf, chunk total A
        float pf = a;
        #pragma unroll
        for (int off = 1; off < 32; off <<= 1) {
            float v = __shfl_up_sync(0xFFFFFFFFu, pf, off);
            if (t >= off) pf *= v;
        }
        sPF[t] = pf;
        if (t == 31) sChunkA = pf;

        // width-8 segmented inclusive product -> subgroup correction weights
        float ps = a;
        #pragma unroll
        for (int off = 1; off < SLEN; off <<= 1) {
            float v = __shfl_up_sync(0xFFFFFFFFu, ps, off, SLEN);
            if ((t & (SLEN - 1)) >= off) ps *= v;
        }
        sSeg[t] = ps;
        if ((t & (SLEN - 1)) == SLEN - 1) sGA[t >> 3] = ps;
    }
    __syncthreads();

    // 3) subgroup zero-start scan
    float4 prev = make_float4(0.f, 0.f, 0.f, 0.f);
    #pragma unroll
    for (int i = 0; i < SLEN; i++) {
        const float a = sa[jb + i], bb = sb[jb + i];
        prev.x = fmaf(a, prev.x, bb * e[i].x);
        prev.y = fmaf(a, prev.y, bb * e[i].y);
        prev.z = fmaf(a, prev.z, bb * e[i].z);
        prev.w = fmaf(a, prev.w, bb * e[i].w);
        e[i] = prev;
    }
    sVec[g][d4] = prev;
    __syncthreads();

    // 4) intra-block carry, applied in-register -> e[] = chunk-local scan
    {
        float4 cg = make_float4(0.f, 0.f, 0.f, 0.f);
        if (g >= 1) cg = sVec[0][d4];
        if (g >= 2) {
            const float4 e1 = sVec[1][d4];
            const float A1 = sGA[1];
            cg.x = fmaf(A1, cg.x, e1.x);
            cg.y = fmaf(A1, cg.y, e1.y);
            cg.z = fmaf(A1, cg.z, e1.z);
            cg.w = fmaf(A1, cg.w, e1.w);
        }
        if (g >= 3) {
            const float4 e2 = sVec[2][d4];
            const float A2 = sGA[2];
            cg.x = fmaf(A2, cg.x, e2.x);
            cg.y = fmaf(A2, cg.y, e2.y);
            cg.z = fmaf(A2, cg.z, e2.z);
            cg.w = fmaf(A2, cg.w, e2.w);
        }
        #pragma unroll
        for (int i = 0; i < SLEN; i++) {
            const float w = sSeg[jb + i];
            e[i].x = fmaf(w, cg.x, e[i].x);
            e[i].y = fmaf(w, cg.y, e[i].y);
            e[i].z = fmaf(w, cg.z, e[i].z);
            e[i].w = fmaf(w, cg.w, e[i].w);
        }
    }

    // 5) publish chunk end + A (release: payload stores, fence, sync, flag)
    if (g == NSG - 1)
        g_partialEnd[(b * NCH + c) * D4 + d4] = e[SLEN - 1];
    __threadfence();
    __syncthreads();
    if (t == 0) {
        unsigned long long v =
            (1ULL << 32) | (unsigned long long)__float_as_uint(sChunkA);
        atomicExch(&g_flag[b * NCH + c], v);
    }

    // 6) lookback: combine ALL predecessor partials (no serial chain)
    float4 carry = make_float4(0.f, 0.f, 0.f, 0.f);
    if (c > 0) {
        if (t < 32) {
            float Ak = 1.0f;
            if (t < c) {
                volatile unsigned long long* vf = &g_flag[b * NCH + t];
                unsigned long long v = *vf;
                while (!(v >> 32)) { __nanosleep(40); v = *vf; }
                Ak = __uint_as_float((unsigned)(v & 0xFFFFFFFFu));
            }
            // suffix products: P_k = prod_{m=k+1..c-1} A_m
            float s = Ak;
            #pragma unroll
            for (int off = 1; off < 32; off <<= 1) {
                float v2 = __shfl_down_sync(0xFFFFFFFFu, s, off);
                if (t + off < c) s *= v2;
            }
            float P = __shfl_down_sync(0xFFFFFFFFu, s, 1);
            if (t + 1 >= c) P = 1.0f;
            sP[t] = P;
        }
        __syncthreads();     // sP ready; sVec free for reuse

        float4 acc = make_float4(0.f, 0.f, 0.f, 0.f);
        #pragma unroll 2
        for (int k = g; k < c; k += NSG) {
            const float4 ev = __ldcg(&g_partialEnd[(b * NCH + k) * D4 + d4]);
            const float Pk = sP[k];
            acc.x = fmaf(Pk, ev.x, acc.x);
            acc.y = fmaf(Pk, ev.y, acc.y);
            acc.z = fmaf(Pk, ev.z, acc.z);
            acc.w = fmaf(Pk, ev.w, acc.w);
        }
        sVec[g][d4] = acc;
        __syncthreads();
        carry = sVec[0][d4];
        #pragma unroll
        for (int g2 = 1; g2 < NSG; g2++) {
            const float4 a2 = sVec[g2][d4];
            carry.x += a2.x; carry.y += a2.y; carry.z += a2.z; carry.w += a2.w;
        }
    }

    // 7) final corrected smoothed: s[j] = e[i] + pf[j] * carry
    float4* sp = g_smoothed + base;
    #pragma unroll
    for (int i = 0; i < SLEN; i++) {
        const float w = sPF[jb + i];
        float4 r;
        r.x = fmaf(w, carry.x, e[i].x);
        r.y = fmaf(w, carry.y, e[i].y);
        r.z = fmaf(w, carry.z, e[i].z);
        r.w = fmaf(w, carry.w, e[i].w);
        sp[(size_t)i * D4] = r;
    }
}

// ---------------------------------------------------------------------------
// Kernel 2: pure copy-gather, one warp per (b,l) row. Also re-zeroes the
// lookback flags for the next graph replay (blocks 0,1).
// out stores are streaming (__stcs): never re-read, keep L2 for smoothed.
// ---------------------------------------------------------------------------
__global__ void k_gather(float4* __restrict__ out) {
    if (blockIdx.x < 2) {
        const int i = blockIdx.x * 256 + threadIdx.x;   // 512 flag words
        g_flag[i] = 0ULL;
    }

    const unsigned int wg = (blockIdx.x * blockDim.x + threadIdx.x) >> 5;
    const int lane = threadIdx.x & 31;
    const int l = wg & (L_ - 1);
    const int b = wg >> 12;

    const int j = g_idx[b * L_ + l];
    const float4* __restrict__ sp = g_smoothed + ((size_t)b * J_ + j) * D4;
    float4* __restrict__ op = out + ((size_t)b * L_ + l) * D4;

    float4 pv[4];
    #pragma unroll
    for (int k = 0; k < 4; k++) pv[k] = sp[k * 32 + lane];
    #pragma unroll
    for (int k = 0; k < 4; k++) __stcs(op + k * 32 + lane, pv[k]);
}

// ---------------------------------------------------------------------------
extern "C" void kernel_launch(void* const* d_in, const int* in_sizes, int n_in,
                              void* d_out, int out_size) {
    const float4* emb  = (const float4*)d_in[0];  // (16,1024,512) f32
    const float*  conf = (const float*)d_in[1];   // (16,1024) f32
    const int*    msk  = (const int*)d_in[2];     // (16,1024) bool->int32
    const int*    bnd  = (const int*)d_in[3];     // (16,4096) bool->int32
    float4* out = (float4*)d_out;                 // (16,4096,512) f32

    k_partial<<<dim3(NCH + 1, B_), 512>>>(emb, conf, msk, bnd);
    k_gather<<<(B_ * L_ * 32) / 256, 256>>>(out);
}